// round 14
// baseline (speedup 1.0000x reference)
#include <cuda_runtime.h>

#define NB 8
#define LPC 2500
#define C_ 14
#define K_ 9
#define N_ (NB*LPC)
#define E_ (N_*K_)
#define HID_ 128
#define NCLS_ 20
#define XDIM 42
#define NPB 10
#define M_ 96
#define NT 192
#define STR 132
#define NNB 16

typedef unsigned long long ull;

__device__ __align__(16) float g_X[2][N_*XDIM];
__device__ __align__(16) float g_h[N_*HID_];
__device__ __align__(16) float g_aggm[N_*HID_];
__device__ int g_dst[E_];
__device__ __align__(16) float g_classh[NCLS_*HID_];
__device__ float g_classcw[NCLS_*C_];
__device__ float g_be1[3][HID_];

// tf32 B-fragment packs (hi plane only, 1xTF32)
__device__ __align__(16) float g_fWr [3][28*1024];
__device__ __align__(16) float g_fWe1[3][48*1024];
__device__ __align__(16) float g_fWe2[3][16*1024];
__device__ __align__(16) float g_fWx1[3][16*1024];
__device__ __align__(16) float g_fWx2[3][16*128];
// f32x2 packs for node/final
__device__ __align__(16) float g_Wh1P[3][64*512];
__device__ __align__(16) float g_Wh2P[3][32*512];
__device__ __align__(16) float g_Wf1P[32*512];
__device__ __align__(16) float g_Wf2T[NCLS_][HID_];

__device__ __forceinline__ float silu_f(float x) {
    return x * (1.0f / (1.0f + __expf(-x)));
}
__device__ __forceinline__ unsigned tf32r(float x) {
    unsigned r; asm("cvt.rna.tf32.f32 %0, %1;" : "=r"(r) : "f"(x)); return r;
}
__device__ __forceinline__ void mma4(float c[4], unsigned a0, unsigned a1,
                                     unsigned a2, unsigned a3,
                                     unsigned b0, unsigned b1) {
    asm volatile(
        "mma.sync.aligned.m16n8k8.row.col.f32.tf32.tf32.f32 "
        "{%0,%1,%2,%3}, {%4,%5,%6,%7}, {%8,%9}, {%0,%1,%2,%3};"
        : "+f"(c[0]), "+f"(c[1]), "+f"(c[2]), "+f"(c[3])
        : "r"(a0), "r"(a1), "r"(a2), "r"(a3), "r"(b0), "r"(b1));
}
__device__ __forceinline__ void fma2(ull& a, ull x, ull w) {
    asm("fma.rn.f32x2 %0, %1, %2, %0;" : "+l"(a) : "l"(x), "l"(w));
}
__device__ __forceinline__ float hadd2(ull v) {
    unsigned lo, hi;
    asm("mov.b64 {%0,%1}, %2;" : "=r"(lo), "=r"(hi) : "l"(v));
    return __uint_as_float(lo) + __uint_as_float(hi);
}
__device__ __forceinline__ ulonglong2 ld2u(const float* p) {
    return *reinterpret_cast<const ulonglong2*>(p);
}
__device__ __forceinline__ void mbar_init(unsigned a, unsigned cnt) {
    asm volatile("mbarrier.init.shared.b64 [%0], %1;" :: "r"(a), "r"(cnt) : "memory");
}
__device__ __forceinline__ void mbar_wait(unsigned a, unsigned par) {
    unsigned done;
    do {
        asm volatile("{\n\t.reg .pred p;\n\t"
            "mbarrier.try_wait.parity.acquire.cta.shared::cta.b64 p, [%1], %2, 0x989680;\n\t"
            "selp.b32 %0, 1, 0, p;\n\t}" : "=r"(done) : "r"(a), "r"(par) : "memory");
    } while (!done);
}
__device__ __forceinline__ void bulk_copy(unsigned dstS, const float* srcG,
                                          unsigned bytes, unsigned mbar) {
    asm volatile("mbarrier.arrive.expect_tx.shared.b64 _, [%0], %1;"
                 :: "r"(mbar), "r"(bytes) : "memory");
    asm volatile("cp.async.bulk.shared::cta.global.mbarrier::complete_tx::bytes "
                 "[%0], [%1], %2, [%3];"
                 :: "r"(dstS), "l"(srcG), "r"(bytes), "r"(mbar) : "memory");
}

// ---------------------------------------------------------------------------
// 2-D tiled 1xTF32 GEMM: warp owns 32 M-rows (2 A-tiles) x 8 ntiles.
// Each B float2 feeds 2 mma -> half the crossbar traffic per MAC.
// ---------------------------------------------------------------------------
__device__ __forceinline__ void gemmT16(
    const float* __restrict__ frag, int kq8, float* wbuf,
    unsigned mb0, unsigned mb1, int* ph,
    const float* p0, const float* p1, const float* p2, const float* p3,
    int nbase, int t, int l, int tid, float (*cc)[2][4])
{
    const int PERQ = 1024, CHQ = 4;
    int nch = (kq8 + CHQ - 1)/CHQ;
    unsigned wbS = (unsigned)__cvta_generic_to_shared(wbuf);
    if (tid == 0)
        bulk_copy(wbS, frag, (unsigned)(min(CHQ, kq8)*PERQ*4), mb0);
    for (int ch = 0; ch < nch; ch++) {
        if (tid == 0 && ch+1 < nch) {
            unsigned nb = (unsigned)(min(CHQ, kq8-(ch+1)*CHQ)*PERQ*4);
            bulk_copy(wbS + ((ch+1)&1)*16384,
                      frag + (size_t)(ch+1)*CHQ*PERQ, nb, ((ch+1)&1) ? mb1 : mb0);
        }
        mbar_wait((ch&1) ? mb1 : mb0, ph[ch&1] & 1);
        ph[ch&1]++;
        const float* wb = wbuf + (ch&1)*4096;
        int qn = min(CHQ, kq8 - ch*CHQ);
        for (int qq = 0; qq < qn; qq++) {
            int q = ch*CHQ + qq;
            unsigned a00 = tf32r(p0[q*8+t]),   a01 = tf32r(p1[q*8+t]);
            unsigned a02 = tf32r(p0[q*8+t+4]), a03 = tf32r(p1[q*8+t+4]);
            unsigned a10 = tf32r(p2[q*8+t]),   a11 = tf32r(p3[q*8+t]);
            unsigned a12 = tf32r(p2[q*8+t+4]), a13 = tf32r(p3[q*8+t+4]);
            const float* whi = wb + qq*PERQ + nbase*64 + l*2;
            #pragma unroll
            for (int n = 0; n < 8; n++) {
                float2 bh = *(const float2*)(whi + n*64);
                unsigned b0 = __float_as_uint(bh.x), b1 = __float_as_uint(bh.y);
                mma4(cc[n][0], a00,a01,a02,a03, b0, b1);
                mma4(cc[n][1], a10,a11,a12,a13, b0, b1);
            }
        }
        __syncthreads();
    }
}

// Old 1-D tiling kept for the small Wx2 GEMM (Nt=2).
template<int NTL>
__device__ __forceinline__ void gemmT(
    const float* __restrict__ frag, int kq8, float* wbuf,
    unsigned mb0, unsigned mb1, int* ph,
    const float* aR0, const float* aR1, int t, int l, int tid, float (*cc)[4])
{
    const int PERQ = NTL*64;
    const int CHQ  = 4096/PERQ;
    int nch = (kq8 + CHQ - 1)/CHQ;
    unsigned wbS = (unsigned)__cvta_generic_to_shared(wbuf);
    if (tid == 0)
        bulk_copy(wbS, frag, (unsigned)(min(CHQ, kq8)*PERQ*4), mb0);
    for (int ch = 0; ch < nch; ch++) {
        if (tid == 0 && ch+1 < nch) {
            unsigned nb = (unsigned)(min(CHQ, kq8-(ch+1)*CHQ)*PERQ*4);
            bulk_copy(wbS + ((ch+1)&1)*16384,
                      frag + (size_t)(ch+1)*CHQ*PERQ, nb, ((ch+1)&1) ? mb1 : mb0);
        }
        mbar_wait((ch&1) ? mb1 : mb0, ph[ch&1] & 1);
        ph[ch&1]++;
        const float* wb = wbuf + (ch&1)*4096;
        int qn = min(CHQ, kq8 - ch*CHQ);
        for (int qq = 0; qq < qn; qq++) {
            int q = ch*CHQ + qq;
            unsigned h0 = tf32r(aR0[q*8+t]);
            unsigned h1 = tf32r(aR1[q*8+t]);
            unsigned h2 = tf32r(aR0[q*8+t+4]);
            unsigned h3 = tf32r(aR1[q*8+t+4]);
            const float* whi = wb + qq*PERQ + l*2;
            #pragma unroll
            for (int n = 0; n < NTL; n++) {
                float2 bh = *(const float2*)(whi + n*64);
                mma4(cc[n], h0,h1,h2,h3,
                     __float_as_uint(bh.x), __float_as_uint(bh.y));
            }
        }
        __syncthreads();
    }
}

#define ZC2() { _Pragma("unroll") for (int n=0;n<8;n++){ \
    cc[n][0][0]=cc[n][0][1]=cc[n][0][2]=cc[n][0][3]=0.f; \
    cc[n][1][0]=cc[n][1][1]=cc[n][1][2]=cc[n][1][3]=0.f; } }
#define EPI2_SILU(dst) { _Pragma("unroll") for (int n=0;n<8;n++){ int col=(nbase+n)*8+2*t; \
    *(float2*)((dst) + ra*STR + col) = make_float2(silu_f(cc[n][0][0]), silu_f(cc[n][0][1])); \
    *(float2*)((dst) + rb*STR + col) = make_float2(silu_f(cc[n][0][2]), silu_f(cc[n][0][3])); \
    *(float2*)((dst) + rc*STR + col) = make_float2(silu_f(cc[n][1][0]), silu_f(cc[n][1][1])); \
    *(float2*)((dst) + rd*STR + col) = make_float2(silu_f(cc[n][1][2]), silu_f(cc[n][1][3])); } }
#define EPI2_RAW(dst) { _Pragma("unroll") for (int n=0;n<8;n++){ int col=(nbase+n)*8+2*t; \
    *(float2*)((dst) + ra*STR + col) = make_float2(cc[n][0][0], cc[n][0][1]); \
    *(float2*)((dst) + rb*STR + col) = make_float2(cc[n][0][2], cc[n][0][3]); \
    *(float2*)((dst) + rc*STR + col) = make_float2(cc[n][1][0], cc[n][1][1]); \
    *(float2*)((dst) + rd*STR + col) = make_float2(cc[n][1][2], cc[n][1][3]); } }

// ---------------------------------------------------------------------------
// Edge kernel: 10 nodes (96 rows) per block; warps tiled 3(M) x 2(N).
// ---------------------------------------------------------------------------
__global__ void __launch_bounds__(NT) edge_kernel(
    int layer, const float* __restrict__ Xext, const int* __restrict__ S)
{
    extern __shared__ float sm[];
    float* sA  = sm;                  // [96][132] hdst -> m
    float* sB  = sA  + M_*STR;        // [96][132] rf -> t
    float* sC  = sB  + M_*STR;        // [96][132] rad scratch -> m1
    float* sW  = sC  + M_*STR;        // 8192 weight ring
    float* sXD = sW  + 8192;          // [96][42]
    float* sHS = sXD + M_*XDIM;       // [12][132] h_src (rows>=10 zero)
    float* sBE = sHS + 12*STR;        // 128 bias
    float* sCW = sBE + 128;           // [96][16] coef
    int* sDST  = (int*)(sCW + M_*16); // [96]
    unsigned mbBase = (unsigned)__cvta_generic_to_shared(sDST + M_);
    unsigned mb0 = mbBase, mb1 = mbBase + 8;

    const float* Xin  = (layer == 0) ? Xext : g_X[(layer + 1) & 1];
    float*       Xout = g_X[layer & 1];
    const int tid = threadIdx.x;
    const int w = tid >> 5, l = tid & 31, t = l & 3, g = l >> 2;
    const int i0 = blockIdx.x * NPB;
    const int mw = w % 3, nh = w / 3;
    const int mrow = mw*32, nbase = nh*8;
    const int ra = mrow + g, rb = ra + 8, rc = ra + 16, rd = ra + 24;
    const int R0 = w*16 + g, R1 = R0 + 8;   // old tiling (Wx2)
    int ph[2] = {0, 0};

    if (tid == 0) { mbar_init(mb0, 1); mbar_init(mb1, 1); }
    if (tid < M_) sDST[tid] = (tid < NPB*K_) ? g_dst[i0*K_ + tid] : i0;
    if (tid < 128) sBE[tid] = g_be1[layer][tid];
    for (int idx = tid; idx < 12*32; idx += NT) {
        int r = idx >> 5, c4 = (idx & 31) << 2;
        float4 v = (r < NPB) ? *(const float4*)(g_h + (size_t)(i0+r)*HID_ + c4)
                             : make_float4(0,0,0,0);
        *(float4*)(sHS + r*STR + c4) = v;
    }
    __syncthreads();
    for (int idx = tid; idx < M_*32; idx += NT) {
        int r = idx >> 5, c4 = (idx & 31) << 2;
        *(float4*)(sA + r*STR + c4) =
            *(const float4*)(g_h + (size_t)sDST[r]*HID_ + c4);
    }
    for (int idx = tid; idx < M_*XDIM; idx += NT) {
        int r = idx / XDIM, q = idx - r*XDIM;
        float v = 0.f;
        if (r < NPB*K_)
            v = Xin[(size_t)(i0 + r/K_)*XDIM + q] - Xin[(size_t)sDST[r]*XDIM + q];
        sXD[r*XDIM + q] = v;
    }
    __syncthreads();

    float cc[8][2][4];

    // ---- rf = rad @ (Wr/14): rad in two K-slices via sC ----
    ZC2();
    for (int idx = tid; idx < M_*128; idx += NT) {
        int r = idx >> 7, k = idx & 127;
        int c = (k*2341) >> 15, d = k - c*C_;
        const float* x = sXD + r*XDIM;
        sC[r*STR + k] = x[3*c]*x[3*d] + x[3*c+1]*x[3*d+1] + x[3*c+2]*x[3*d+2];
    }
    __syncthreads();
    gemmT16(g_fWr[layer], 16, sW, mb0, mb1, ph,
            sC + ra*STR, sC + rb*STR, sC + rc*STR, sC + rd*STR,
            nbase, t, l, tid, cc);
    for (int idx = tid; idx < M_*68; idx += NT) {
        int r = idx / 68, j = idx - r*68, k = 128 + j;
        int c = (k*2341) >> 15, d = k - c*C_;
        const float* x = sXD + r*XDIM;
        sC[r*STR + j] = x[3*c]*x[3*d] + x[3*c+1]*x[3*d+1] + x[3*c+2]*x[3*d+2];
    }
    __syncthreads();
    gemmT16(g_fWr[layer] + 16*1024, 12, sW, mb0, mb1, ph,
            sC + ra*STR, sC + rb*STR, sC + rc*STR, sC + rd*STR,
            nbase, t, l, tid, cc);
    EPI2_RAW(sB);

    // ---- m1 = silu(be1 + hsrc@W + hdst@W + rf@W) -> sC ----
    #pragma unroll
    for (int n = 0; n < 8; n++) {
        int col = (nbase+n)*8 + 2*t;
        float b0 = sBE[col], b1 = sBE[col+1];
        cc[n][0][0] = b0; cc[n][0][1] = b1; cc[n][0][2] = b0; cc[n][0][3] = b1;
        cc[n][1][0] = b0; cc[n][1][1] = b1; cc[n][1][2] = b0; cc[n][1][3] = b1;
    }
    __syncthreads();   // rf (sB) writes visible to all warps
    gemmT16(g_fWe1[layer], 16, sW, mb0, mb1, ph,
            sHS + (ra/K_)*STR, sHS + (rb/K_)*STR, sHS + (rc/K_)*STR, sHS + (rd/K_)*STR,
            nbase, t, l, tid, cc);
    gemmT16(g_fWe1[layer] + 16*1024, 16, sW, mb0, mb1, ph,
            sA + ra*STR, sA + rb*STR, sA + rc*STR, sA + rd*STR,
            nbase, t, l, tid, cc);
    gemmT16(g_fWe1[layer] + 32*1024, 16, sW, mb0, mb1, ph,
            sB + ra*STR, sB + rb*STR, sB + rc*STR, sB + rd*STR,
            nbase, t, l, tid, cc);
    EPI2_SILU(sC);
    __syncthreads();

    // ---- m = silu(m1 @ We2) -> sA ; aggm ----
    ZC2();
    gemmT16(g_fWe2[layer], 16, sW, mb0, mb1, ph,
            sC + ra*STR, sC + rb*STR, sC + rc*STR, sC + rd*STR,
            nbase, t, l, tid, cc);
    EPI2_SILU(sA);
    __syncthreads();
    for (int idx = tid; idx < NPB*HID_; idx += NT) {
        int p = idx >> 7, c = idx & 127;
        float am = 0.f;
        #pragma unroll
        for (int e = 0; e < K_; e++) am += sA[(p*K_ + e)*STR + c];
        g_aggm[(size_t)(i0+p)*HID_ + c] = am;
    }

    // ---- t = silu(m @ Wx1) -> sB ----
    ZC2();
    gemmT16(g_fWx1[layer], 16, sW, mb0, mb1, ph,
            sA + ra*STR, sA + rb*STR, sA + rc*STR, sA + rd*STR,
            nbase, t, l, tid, cc);
    EPI2_SILU(sB);
    __syncthreads();

    // ---- coef = t @ Wx2 (Nt=2, old tiling) -> sCW ----
    {
        float c2[2][4];
        c2[0][0]=c2[0][1]=c2[0][2]=c2[0][3]=0.f;
        c2[1][0]=c2[1][1]=c2[1][2]=c2[1][3]=0.f;
        gemmT<2>(g_fWx2[layer], 16, sW, mb0, mb1, ph,
                 sB + R0*STR, sB + R1*STR, t, l, tid, c2);
        #pragma unroll
        for (int n = 0; n < 2; n++) {
            int col = n*8 + 2*t;
            *(float2*)(sCW + R0*16 + col) = make_float2(c2[n][0], c2[n][1]);
            *(float2*)(sCW + R1*16 + col) = make_float2(c2[n][2], c2[n][3]);
        }
    }
    __syncthreads();

    // ---- X update ----
    for (int idx = tid; idx < NPB*XDIM; idx += NT) {
        int p = idx / XDIM, q = idx - p*XDIM, c = q / 3;
        float s = 0.f;
        #pragma unroll
        for (int e = 0; e < K_; e++)
            s += sXD[(p*K_ + e)*XDIM + q] * sCW[(p*K_ + e)*16 + c];
        float cw = g_classcw[S[i0+p]*C_ + c];
        Xout[(size_t)(i0+p)*XDIM + q] =
            Xin[(size_t)(i0+p)*XDIM + q] + s * cw * (1.0f/K_);
    }
}

// ---------------------------------------------------------------------------
// Unified pack kernel: fragment packs + f32x2 packs + class tables (one launch
// so edge_kernel is the 4th launch and gets the ncu capture slot).
// ---------------------------------------------------------------------------
__device__ __forceinline__ void pack_frag_one(
    float* dst, const float* __restrict__ W, int f,
    int Ntl, int Kreal, int Ncol, float scale)
{
    int PERQ = Ntl*64;
    int q = f / PERQ, r = f - q*PERQ;
    int n = r >> 6, l2 = r & 63, li = l2 >> 1, b = l2 & 1;
    int t = li & 3, g = li >> 2;
    int k = q*8 + t + b*4, col = n*8 + g;
    float v = (k < Kreal && col < Ncol) ? W[k*Ncol + col] * scale : 0.f;
    dst[f] = __uint_as_float(tf32r(v));
}

__global__ void __launch_bounds__(256) pack_all(
    const float* __restrict__ Wr,  const float* __restrict__ We1,
    const float* __restrict__ We2, const float* __restrict__ Wx1,
    const float* __restrict__ Wx2, const float* __restrict__ Wh1,
    const float* __restrict__ Wh2, const float* __restrict__ Wf1,
    const float* __restrict__ Wf2, const float* __restrict__ be1,
    const float* __restrict__ E_tab, const float* __restrict__ Win,
    const float* __restrict__ Wchan)
{
    int idx = blockIdx.x*256 + threadIdx.x;
    const int S1 = 28*1024, S2 = 48*1024, S3 = 16*1024, S4 = 16*1024, S5 = 16*128;
    const int PL = S1 + S2 + S3 + S4 + S5;      // 112640 per layer
    if (idx < 3*PL) {
        int lyr = idx / PL, f = idx - lyr*PL;
        if (f < S1) { pack_frag_one(g_fWr[lyr],  Wr  + (size_t)lyr*196*128, f, 16, 196, 128, 1.0f/C_); return; }
        f -= S1;
        if (f < S2) { pack_frag_one(g_fWe1[lyr], We1 + (size_t)lyr*384*128, f, 16, 384, 128, 1.f); return; }
        f -= S2;
        if (f < S3) { pack_frag_one(g_fWe2[lyr], We2 + (size_t)lyr*128*128, f, 16, 128, 128, 1.f); return; }
        f -= S3;
        if (f < S4) { pack_frag_one(g_fWx1[lyr], Wx1 + (size_t)lyr*128*128, f, 16, 128, 128, 1.f); return; }
        f -= S4;
        pack_frag_one(g_fWx2[lyr], Wx2 + (size_t)lyr*128*C_, f, 2, 128, C_, 1.f);
        return;
    }
    idx -= 3*PL;
    if (idx < 3*256*128) {
        int lyr = idx / 32768, r = idx & 32767, k = r >> 7, c = r & 127;
        g_Wh1P[lyr][(k>>2)*512 + (c<<2) + (k&3)] = Wh1[idx]; return;
    }
    idx -= 3*256*128;
    if (idx < 3*128*128) {
        int lyr = idx / 16384, r = idx & 16383, k = r >> 7, c = r & 127;
        g_Wh2P[lyr][(k>>2)*512 + (c<<2) + (k&3)] = Wh2[idx]; return;
    }
    idx -= 3*128*128;
    if (idx < 128*128) {
        int k = idx >> 7, c = idx & 127;
        g_Wf1P[(k>>2)*512 + (c<<2) + (k&3)] = Wf1[idx]; return;
    }
    idx -= 128*128;
    if (idx < 128*NCLS_) {
        int k = idx / NCLS_, c = idx - k*NCLS_;
        g_Wf2T[c][k] = Wf2[idx]; return;
    }
    idx -= 128*NCLS_;
    if (idx < 3*HID_) {
        g_be1[idx/HID_][idx%HID_] = be1[idx]; return;
    }
    idx -= 3*HID_;
    if (idx < NCLS_*HID_) {
        int c = idx >> 7, j = idx & 127;
        float acc = 0.f;
        #pragma unroll 4
        for (int k = 0; k < HID_; k++) acc += E_tab[c*HID_ + k] * Win[k*HID_ + j];
        g_classh[c*HID_ + j] = acc;
        return;
    }
    idx -= NCLS_*HID_;
    if (idx < NCLS_) {
        int c = idx;
        float wv[C_]; float mx = -1e30f;
        #pragma unroll
        for (int a = 0; a < C_; a++) { wv[a] = Wchan[c*C_ + a]; mx = fmaxf(mx, wv[a]); }
        float s = 0.f;
        #pragma unroll
        for (int a = 0; a < C_; a++) { wv[a] = expf(wv[a] - mx); s += wv[a]; }
        float inv = 1.0f / s;
        #pragma unroll
        for (int a = 0; a < C_; a++) g_classcw[c*C_ + a] = wv[a] * inv;
    }
}
#define PACK_TOTAL (3*(28*1024+48*1024+16*1024+16*1024+16*128) + 3*256*128 + 3*128*128 + 128*128 + 128*NCLS_ + 3*HID_ + NCLS_*HID_ + NCLS_)

// ---------------------------------------------------------------------------
// kNN on CA coords (channel 1)
// ---------------------------------------------------------------------------
__global__ void __launch_bounds__(256) knn_kernel(const float* __restrict__ X) {
    int b = blockIdx.y;
    int q = blockIdx.x * 256 + threadIdx.x;
    __shared__ float sx[256], sy[256], sz[256];
    float qx = 0.f, qy = 0.f, qz = 0.f;
    if (q < LPC) {
        const float* p = X + ((size_t)(b*LPC + q) * C_ + 1) * 3;
        qx = p[0]; qy = p[1]; qz = p[2];
    }
    float best[K_]; int bidx[K_];
    #pragma unroll
    for (int k = 0; k < K_; k++) { best[k] = 3.0e38f; bidx[k] = 0; }
    for (int base = 0; base < LPC; base += 256) {
        int c = base + threadIdx.x;
        if (c < LPC) {
            const float* p = X + ((size_t)(b*LPC + c) * C_ + 1) * 3;
            sx[threadIdx.x] = p[0]; sy[threadIdx.x] = p[1]; sz[threadIdx.x] = p[2];
        }
        __syncthreads();
        int tl = min(256, LPC - base);
        if (q < LPC) {
            for (int j = 0; j < tl; j++) {
                int cj = base + j;
                if (cj == q) continue;
                float dx = qx - sx[j], dy = qy - sy[j], dz = qz - sz[j];
                float d2 = dx*dx + dy*dy + dz*dz;
                if (d2 < best[K_-1]) {
                    int pos = K_-1;
                    while (pos > 0 && best[pos-1] > d2) {
                        best[pos] = best[pos-1]; bidx[pos] = bidx[pos-1]; pos--;
                    }
                    best[pos] = d2; bidx[pos] = cj;
                }
            }
        }
        __syncthreads();
    }
    if (q < LPC) {
        int n = b*LPC + q;
        #pragma unroll
        for (int k = 0; k < K_; k++) g_dst[n*K_ + k] = b*LPC + bidx[k];
    }
}

__global__ void __launch_bounds__(256) gather_h_kernel(const int* __restrict__ S) {
    int idx = blockIdx.x * 256 + threadIdx.x;
    if (idx < N_ * HID_) {
        int i = idx >> 7, j = idx & 127;
        g_h[idx] = g_classh[S[i]*HID_ + j];
    }
}

// ---------------------------------------------------------------------------
// Node update (f32x2, 16 nodes/block)
// ---------------------------------------------------------------------------
__global__ void __launch_bounds__(128) node_kernel(int layer) {
    const float* W1P = g_Wh1P[layer];
    const float* W2P = g_Wh2P[layer];
    int i0 = blockIdx.x * NNB, tid = threadIdx.x;
    __shared__ __align__(16) float s_h[NNB][HID_];
    __shared__ __align__(16) float s_am[NNB][HID_];
    __shared__ __align__(16) float s_u[NNB][HID_];
    #pragma unroll
    for (int r = 0; r < NNB; r++) {
        s_h[r][tid]  = g_h[(i0+r)*HID_ + tid];
        s_am[r][tid] = g_aggm[(i0+r)*HID_ + tid];
    }
    __syncthreads();
    {
        ull acc[NNB];
        #pragma unroll
        for (int r = 0; r < NNB; r++) acc[r] = 0ULL;
        const float* wp = W1P + (tid << 2);
        #pragma unroll 1
        for (int k4 = 0; k4 < 32; k4++) {
            ulonglong2 wv = ld2u(wp + k4*512);
            #pragma unroll
            for (int r = 0; r < NNB; r++) {
                ulonglong2 a = ld2u(&s_h[r][k4 << 2]);
                fma2(acc[r], a.x, wv.x); fma2(acc[r], a.y, wv.y);
            }
        }
        const float* wp2 = W1P + 32*512 + (tid << 2);
        #pragma unroll 1
        for (int k4 = 0; k4 < 32; k4++) {
            ulonglong2 wv = ld2u(wp2 + k4*512);
            #pragma unroll
            for (int r = 0; r < NNB; r++) {
                ulonglong2 a = ld2u(&s_am[r][k4 << 2]);
                fma2(acc[r], a.x, wv.x); fma2(acc[r], a.y, wv.y);
            }
        }
        #pragma unroll
        for (int r = 0; r < NNB; r++) s_u[r][tid] = silu_f(hadd2(acc[r]));
    }
    __syncthreads();
    {
        ull acc[NNB];
        #pragma unroll
        for (int r = 0; r < NNB; r++) acc[r] = 0ULL;
        const float* wp = W2P + (tid << 2);
        #pragma unroll 1
        for (int k4 = 0; k4 < 32; k4++) {
            ulonglong2 wv = ld2u(wp + k4*512);
            #pragma unroll
            for (int r = 0; r < NNB; r++) {
                ulonglong2 a = ld2u(&s_u[r][k4 << 2]);
                fma2(acc[r], a.x, wv.x); fma2(acc[r], a.y, wv.y);
            }
        }
        #pragma unroll
        for (int r = 0; r < NNB; r++)
            g_h[(i0+r)*HID_ + tid] = s_h[r][tid] + hadd2(acc[r]);
    }
}

__global__ void __launch_bounds__(128) final_kernel(float* __restrict__ out) {
    int i0 = blockIdx.x * NNB, tid = threadIdx.x;
    __shared__ __align__(16) float s1[NNB][HID_];
    __shared__ __align__(16) float s_u[NNB][HID_];
    #pragma unroll
    for (int r = 0; r < NNB; r++)
        s1[r][tid] = silu_f(g_h[(i0+r)*HID_ + tid]);
    __syncthreads();
    {
        ull acc[NNB];
        #pragma unroll
        for (int r = 0; r < NNB; r++) acc[r] = 0ULL;
        const float* wp = g_Wf1P + (tid << 2);
        #pragma unroll 1
        for (int k4 = 0; k4 < 32; k4++) {
            ulonglong2 wv = ld2u(wp + k4*512);
            #pragma unroll
            for (int r = 0; r < NNB; r++) {
                ulonglong2 a = ld2u(&s1[r][k4 << 2]);
                fma2(acc[r], a.x, wv.x); fma2(acc[r], a.y, wv.y);
            }
        }
        #pragma unroll
        for (int r = 0; r < NNB; r++) s_u[r][tid] = silu_f(hadd2(acc[r]));
    }
    __syncthreads();
    for (int q = tid; q < NNB*NCLS_; q += 128) {
        int r = q / NCLS_, c = q - r*NCLS_;
        ull a2 = 0ULL;
        const float* wrow = &g_Wf2T[c][0];
        #pragma unroll 1
        for (int k4 = 0; k4 < 32; k4++) {
            ulonglong2 wv = ld2u(wrow + (k4 << 2));
            ulonglong2 a = ld2u(&s_u[r][k4 << 2]);
            fma2(a2, a.x, wv.x); fma2(a2, a.y, wv.y);
        }
        out[(size_t)(i0+r)*NCLS_ + c] = hadd2(a2);
    }
    const float* Xf = g_X[0];
    for (int idx = tid; idx < NNB*XDIM; idx += 128)
        out[(size_t)N_*NCLS_ + (size_t)i0*XDIM + idx] = Xf[(size_t)i0*XDIM + idx];
}

// ---------------------------------------------------------------------------
#define SMEM_EDGE ((3*M_*STR + 8192 + M_*XDIM + 12*STR + 128 + M_*16)*4 + M_*4 + 16)

extern "C" void kernel_launch(void* const* d_in, const int* in_sizes, int n_in,
                              void* d_out, int out_size)
{
    const float* X     = (const float*)d_in[0];
    const int*   S     = (const int*)  d_in[1];
    const float* E_tab = (const float*)d_in[2];
    const float* Wchan = (const float*)d_in[3];
    const float* Win   = (const float*)d_in[4];
    const float* Wr    = (const float*)d_in[5];
    const float* We1   = (const float*)d_in[6];
    const float* be1   = (const float*)d_in[7];
    const float* We2   = (const float*)d_in[8];
    const float* Wx1   = (const float*)d_in[9];
    const float* Wx2   = (const float*)d_in[10];
    const float* Wh1   = (const float*)d_in[11];
    const float* Wh2   = (const float*)d_in[12];
    const float* Wf1   = (const float*)d_in[13];
    const float* Wf2   = (const float*)d_in[14];
    float* out = (float*)d_out;

    static int smem_set = 0;
    if (!smem_set) {
        cudaFuncSetAttribute(edge_kernel,
            cudaFuncAttributeMaxDynamicSharedMemorySize, SMEM_EDGE);
        smem_set = 1;
    }

    // Launch order: pack_all(1), knn(2), gather(3), edge(4) <- ncu capture slot
    pack_all<<<(PACK_TOTAL + 255)/256, 256>>>(
        Wr, We1, We2, Wx1, Wx2, Wh1, Wh2, Wf1, Wf2, be1, E_tab, Win, Wchan);
    dim3 kg((LPC + 255) / 256, NB);
    knn_kernel<<<kg, 256>>>(X);
    gather_h_kernel<<<(N_*HID_ + 255) / 256, 256>>>(S);

    for (int l = 0; l < 3; l++) {
        edge_kernel<<<N_/NPB, NT, SMEM_EDGE>>>(l, X, S);
        node_kernel<<<N_/NNB, 128>>>(l);
    }
    final_kernel<<<N_/NNB, 128>>>(out);
}

// round 15
// speedup vs baseline: 1.2828x; 1.2828x over previous
#include <cuda_runtime.h>

#define NB 8
#define LPC 2500
#define C_ 14
#define K_ 9
#define N_ (NB*LPC)
#define E_ (N_*K_)
#define HID_ 128
#define NCLS_ 20
#define XDIM 42
#define NPB 10
#define M_ 96
#define NT 384
#define STR 132
#define NNB 16

typedef unsigned long long ull;

__device__ __align__(16) float g_X[2][N_*XDIM];
__device__ __align__(16) float g_h[N_*HID_];
__device__ __align__(16) float g_aggm[N_*HID_];
__device__ int g_dst[E_];
__device__ __align__(16) float g_classh[NCLS_*HID_];
__device__ float g_classcw[NCLS_*C_];
__device__ float g_be1[3][HID_];

// tf32 B-fragment packs (hi plane only, 1xTF32)
__device__ __align__(16) float g_fWr [3][28*1024];
__device__ __align__(16) float g_fWe1[3][48*1024];
__device__ __align__(16) float g_fWe2[3][16*1024];
__device__ __align__(16) float g_fWx1[3][16*1024];
__device__ __align__(16) float g_fWx2[3][16*128];
// f32x2 packs for node/final
__device__ __align__(16) float g_Wh1P[3][64*512];
__device__ __align__(16) float g_Wh2P[3][32*512];
__device__ __align__(16) float g_Wf1P[32*512];
__device__ __align__(16) float g_Wf2T[NCLS_][HID_];

__device__ __forceinline__ float silu_f(float x) {
    return x * (1.0f / (1.0f + __expf(-x)));
}
__device__ __forceinline__ unsigned tf32r(float x) {
    unsigned r; asm("cvt.rna.tf32.f32 %0, %1;" : "=r"(r) : "f"(x)); return r;
}
__device__ __forceinline__ void mma4(float c[4], unsigned a0, unsigned a1,
                                     unsigned a2, unsigned a3,
                                     unsigned b0, unsigned b1) {
    asm volatile(
        "mma.sync.aligned.m16n8k8.row.col.f32.tf32.tf32.f32 "
        "{%0,%1,%2,%3}, {%4,%5,%6,%7}, {%8,%9}, {%0,%1,%2,%3};"
        : "+f"(c[0]), "+f"(c[1]), "+f"(c[2]), "+f"(c[3])
        : "r"(a0), "r"(a1), "r"(a2), "r"(a3), "r"(b0), "r"(b1));
}
__device__ __forceinline__ void fma2(ull& a, ull x, ull w) {
    asm("fma.rn.f32x2 %0, %1, %2, %0;" : "+l"(a) : "l"(x), "l"(w));
}
__device__ __forceinline__ float hadd2(ull v) {
    unsigned lo, hi;
    asm("mov.b64 {%0,%1}, %2;" : "=r"(lo), "=r"(hi) : "l"(v));
    return __uint_as_float(lo) + __uint_as_float(hi);
}
__device__ __forceinline__ ulonglong2 ld2u(const float* p) {
    return *reinterpret_cast<const ulonglong2*>(p);
}
__device__ __forceinline__ void mbar_init(unsigned a, unsigned cnt) {
    asm volatile("mbarrier.init.shared.b64 [%0], %1;" :: "r"(a), "r"(cnt) : "memory");
}
__device__ __forceinline__ void mbar_wait(unsigned a, unsigned par) {
    unsigned done;
    do {
        asm volatile("{\n\t.reg .pred p;\n\t"
            "mbarrier.try_wait.parity.acquire.cta.shared::cta.b64 p, [%1], %2, 0x989680;\n\t"
            "selp.b32 %0, 1, 0, p;\n\t}" : "=r"(done) : "r"(a), "r"(par) : "memory");
    } while (!done);
}
__device__ __forceinline__ void bulk_copy(unsigned dstS, const float* srcG,
                                          unsigned bytes, unsigned mbar) {
    asm volatile("mbarrier.arrive.expect_tx.shared.b64 _, [%0], %1;"
                 :: "r"(mbar), "r"(bytes) : "memory");
    asm volatile("cp.async.bulk.shared::cta.global.mbarrier::complete_tx::bytes "
                 "[%0], [%1], %2, [%3];"
                 :: "r"(dstS), "l"(srcG), "r"(bytes), "r"(mbar) : "memory");
}

// ---------------------------------------------------------------------------
// 2-D tiled 1xTF32 GEMM, 12 warps as 3(M) x 4(N): warp owns 32 M-rows x 4 ntiles.
// ---------------------------------------------------------------------------
__device__ __forceinline__ void gemmT16(
    const float* __restrict__ frag, int kq8, float* wbuf,
    unsigned mb0, unsigned mb1, int* ph,
    const float* p0, const float* p1, const float* p2, const float* p3,
    int nbase, int t, int l, int tid, float (*cc)[2][4])
{
    const int PERQ = 1024, CHQ = 4;
    int nch = (kq8 + CHQ - 1)/CHQ;
    unsigned wbS = (unsigned)__cvta_generic_to_shared(wbuf);
    if (tid == 0)
        bulk_copy(wbS, frag, (unsigned)(min(CHQ, kq8)*PERQ*4), mb0);
    for (int ch = 0; ch < nch; ch++) {
        if (tid == 0 && ch+1 < nch) {
            unsigned nb = (unsigned)(min(CHQ, kq8-(ch+1)*CHQ)*PERQ*4);
            bulk_copy(wbS + ((ch+1)&1)*16384,
                      frag + (size_t)(ch+1)*CHQ*PERQ, nb, ((ch+1)&1) ? mb1 : mb0);
        }
        mbar_wait((ch&1) ? mb1 : mb0, ph[ch&1] & 1);
        ph[ch&1]++;
        const float* wb = wbuf + (ch&1)*4096;
        int qn = min(CHQ, kq8 - ch*CHQ);
        for (int qq = 0; qq < qn; qq++) {
            int q = ch*CHQ + qq;
            unsigned a00 = tf32r(p0[q*8+t]),   a01 = tf32r(p1[q*8+t]);
            unsigned a02 = tf32r(p0[q*8+t+4]), a03 = tf32r(p1[q*8+t+4]);
            unsigned a10 = tf32r(p2[q*8+t]),   a11 = tf32r(p3[q*8+t]);
            unsigned a12 = tf32r(p2[q*8+t+4]), a13 = tf32r(p3[q*8+t+4]);
            const float* whi = wb + qq*PERQ + nbase*64 + l*2;
            #pragma unroll
            for (int n = 0; n < 4; n++) {
                float2 bh = *(const float2*)(whi + n*64);
                unsigned b0 = __float_as_uint(bh.x), b1 = __float_as_uint(bh.y);
                mma4(cc[n][0], a00,a01,a02,a03, b0, b1);
                mma4(cc[n][1], a10,a11,a12,a13, b0, b1);
            }
        }
        __syncthreads();
    }
}

// Old 1-D tiling for the small Wx2 GEMM (Nt=2); warps 6..11 duplicate warps 0..5.
template<int NTL>
__device__ __forceinline__ void gemmT(
    const float* __restrict__ frag, int kq8, float* wbuf,
    unsigned mb0, unsigned mb1, int* ph,
    const float* aR0, const float* aR1, int t, int l, int tid, float (*cc)[4])
{
    const int PERQ = NTL*64;
    const int CHQ  = 4096/PERQ;
    int nch = (kq8 + CHQ - 1)/CHQ;
    unsigned wbS = (unsigned)__cvta_generic_to_shared(wbuf);
    if (tid == 0)
        bulk_copy(wbS, frag, (unsigned)(min(CHQ, kq8)*PERQ*4), mb0);
    for (int ch = 0; ch < nch; ch++) {
        if (tid == 0 && ch+1 < nch) {
            unsigned nb = (unsigned)(min(CHQ, kq8-(ch+1)*CHQ)*PERQ*4);
            bulk_copy(wbS + ((ch+1)&1)*16384,
                      frag + (size_t)(ch+1)*CHQ*PERQ, nb, ((ch+1)&1) ? mb1 : mb0);
        }
        mbar_wait((ch&1) ? mb1 : mb0, ph[ch&1] & 1);
        ph[ch&1]++;
        const float* wb = wbuf + (ch&1)*4096;
        int qn = min(CHQ, kq8 - ch*CHQ);
        for (int qq = 0; qq < qn; qq++) {
            int q = ch*CHQ + qq;
            unsigned h0 = tf32r(aR0[q*8+t]);
            unsigned h1 = tf32r(aR1[q*8+t]);
            unsigned h2 = tf32r(aR0[q*8+t+4]);
            unsigned h3 = tf32r(aR1[q*8+t+4]);
            const float* whi = wb + qq*PERQ + l*2;
            #pragma unroll
            for (int n = 0; n < NTL; n++) {
                float2 bh = *(const float2*)(whi + n*64);
                mma4(cc[n], h0,h1,h2,h3,
                     __float_as_uint(bh.x), __float_as_uint(bh.y));
            }
        }
        __syncthreads();
    }
}

#define ZC2() { _Pragma("unroll") for (int n=0;n<4;n++){ \
    cc[n][0][0]=cc[n][0][1]=cc[n][0][2]=cc[n][0][3]=0.f; \
    cc[n][1][0]=cc[n][1][1]=cc[n][1][2]=cc[n][1][3]=0.f; } }
#define EPI2_SILU(dst) { _Pragma("unroll") for (int n=0;n<4;n++){ int col=(nbase+n)*8+2*t; \
    *(float2*)((dst) + ra*STR + col) = make_float2(silu_f(cc[n][0][0]), silu_f(cc[n][0][1])); \
    *(float2*)((dst) + rb*STR + col) = make_float2(silu_f(cc[n][0][2]), silu_f(cc[n][0][3])); \
    *(float2*)((dst) + rc*STR + col) = make_float2(silu_f(cc[n][1][0]), silu_f(cc[n][1][1])); \
    *(float2*)((dst) + rd*STR + col) = make_float2(silu_f(cc[n][1][2]), silu_f(cc[n][1][3])); } }
#define EPI2_RAW(dst) { _Pragma("unroll") for (int n=0;n<4;n++){ int col=(nbase+n)*8+2*t; \
    *(float2*)((dst) + ra*STR + col) = make_float2(cc[n][0][0], cc[n][0][1]); \
    *(float2*)((dst) + rb*STR + col) = make_float2(cc[n][0][2], cc[n][0][3]); \
    *(float2*)((dst) + rc*STR + col) = make_float2(cc[n][1][0], cc[n][1][1]); \
    *(float2*)((dst) + rd*STR + col) = make_float2(cc[n][1][2], cc[n][1][3]); } }

// ---------------------------------------------------------------------------
// Edge kernel: 10 nodes (96 rows) per block; 12 warps tiled 3(M) x 4(N).
// ---------------------------------------------------------------------------
__global__ void __launch_bounds__(NT) edge_kernel(
    int layer, const float* __restrict__ Xext, const int* __restrict__ S)
{
    extern __shared__ float sm[];
    float* sA  = sm;                  // [96][132] hdst -> m
    float* sB  = sA  + M_*STR;        // [96][132] rf -> t
    float* sC  = sB  + M_*STR;        // [96][132] rad scratch -> m1
    float* sW  = sC  + M_*STR;        // 8192 weight ring
    float* sXD = sW  + 8192;          // [96][42]
    float* sHS = sXD + M_*XDIM;       // [12][132] h_src (rows>=10 zero)
    float* sBE = sHS + 12*STR;        // 128 bias
    float* sCW = sBE + 128;           // [96][16] coef
    int* sDST  = (int*)(sCW + M_*16); // [96]
    unsigned mbBase = (unsigned)__cvta_generic_to_shared(sDST + M_);
    unsigned mb0 = mbBase, mb1 = mbBase + 8;

    const float* Xin  = (layer == 0) ? Xext : g_X[(layer + 1) & 1];
    float*       Xout = g_X[layer & 1];
    const int tid = threadIdx.x;
    const int w = tid >> 5, l = tid & 31, t = l & 3, g = l >> 2;
    const int i0 = blockIdx.x * NPB;
    const int mw = w % 3, nh = w / 3;            // 3 M-groups x 4 N-groups
    const int mrow = mw*32, nbase = nh*4;        // 4 ntiles (32 cols) per warp
    const int ra = mrow + g, rb = ra + 8, rc = ra + 16, rd = ra + 24;
    const int R0 = (w % 6)*16 + g, R1 = R0 + 8;  // Wx2 old tiling (dup across halves)
    int ph[2] = {0, 0};

    if (tid == 0) { mbar_init(mb0, 1); mbar_init(mb1, 1); }
    if (tid < M_) sDST[tid] = (tid < NPB*K_) ? g_dst[i0*K_ + tid] : i0;
    if (tid >= 128 && tid < 256) sBE[tid-128] = g_be1[layer][tid-128];
    for (int idx = tid; idx < 12*32; idx += NT) {
        int r = idx >> 5, c4 = (idx & 31) << 2;
        float4 v = (r < NPB) ? *(const float4*)(g_h + (size_t)(i0+r)*HID_ + c4)
                             : make_float4(0,0,0,0);
        *(float4*)(sHS + r*STR + c4) = v;
    }
    __syncthreads();
    for (int idx = tid; idx < M_*32; idx += NT) {
        int r = idx >> 5, c4 = (idx & 31) << 2;
        *(float4*)(sA + r*STR + c4) =
            *(const float4*)(g_h + (size_t)sDST[r]*HID_ + c4);
    }
    for (int idx = tid; idx < M_*XDIM; idx += NT) {
        int r = idx / XDIM, q = idx - r*XDIM;
        float v = 0.f;
        if (r < NPB*K_)
            v = Xin[(size_t)(i0 + r/K_)*XDIM + q] - Xin[(size_t)sDST[r]*XDIM + q];
        sXD[r*XDIM + q] = v;
    }
    __syncthreads();

    float cc[4][2][4];

    // ---- rf = rad @ (Wr/14): rad in two K-slices via sC ----
    ZC2();
    for (int idx = tid; idx < M_*128; idx += NT) {
        int r = idx >> 7, k = idx & 127;
        int c = (k*2341) >> 15, d = k - c*C_;
        const float* x = sXD + r*XDIM;
        sC[r*STR + k] = x[3*c]*x[3*d] + x[3*c+1]*x[3*d+1] + x[3*c+2]*x[3*d+2];
    }
    __syncthreads();
    gemmT16(g_fWr[layer], 16, sW, mb0, mb1, ph,
            sC + ra*STR, sC + rb*STR, sC + rc*STR, sC + rd*STR,
            nbase, t, l, tid, cc);
    for (int idx = tid; idx < M_*68; idx += NT) {
        int r = idx / 68, j = idx - r*68, k = 128 + j;
        int c = (k*2341) >> 15, d = k - c*C_;
        const float* x = sXD + r*XDIM;
        sC[r*STR + j] = x[3*c]*x[3*d] + x[3*c+1]*x[3*d+1] + x[3*c+2]*x[3*d+2];
    }
    __syncthreads();
    gemmT16(g_fWr[layer] + 16*1024, 12, sW, mb0, mb1, ph,
            sC + ra*STR, sC + rb*STR, sC + rc*STR, sC + rd*STR,
            nbase, t, l, tid, cc);
    EPI2_RAW(sB);

    // ---- m1 = silu(be1 + hsrc@W + hdst@W + rf@W) -> sC ----
    #pragma unroll
    for (int n = 0; n < 4; n++) {
        int col = (nbase+n)*8 + 2*t;
        float b0 = sBE[col], b1 = sBE[col+1];
        cc[n][0][0] = b0; cc[n][0][1] = b1; cc[n][0][2] = b0; cc[n][0][3] = b1;
        cc[n][1][0] = b0; cc[n][1][1] = b1; cc[n][1][2] = b0; cc[n][1][3] = b1;
    }
    __syncthreads();   // rf (sB) writes visible to all warps
    gemmT16(g_fWe1[layer], 16, sW, mb0, mb1, ph,
            sHS + (ra/K_)*STR, sHS + (rb/K_)*STR, sHS + (rc/K_)*STR, sHS + (rd/K_)*STR,
            nbase, t, l, tid, cc);
    gemmT16(g_fWe1[layer] + 16*1024, 16, sW, mb0, mb1, ph,
            sA + ra*STR, sA + rb*STR, sA + rc*STR, sA + rd*STR,
            nbase, t, l, tid, cc);
    gemmT16(g_fWe1[layer] + 32*1024, 16, sW, mb0, mb1, ph,
            sB + ra*STR, sB + rb*STR, sB + rc*STR, sB + rd*STR,
            nbase, t, l, tid, cc);
    EPI2_SILU(sC);
    __syncthreads();

    // ---- m = silu(m1 @ We2) -> sA ; aggm ----
    ZC2();
    gemmT16(g_fWe2[layer], 16, sW, mb0, mb1, ph,
            sC + ra*STR, sC + rb*STR, sC + rc*STR, sC + rd*STR,
            nbase, t, l, tid, cc);
    EPI2_SILU(sA);
    __syncthreads();
    for (int idx = tid; idx < NPB*HID_; idx += NT) {
        int p = idx >> 7, c = idx & 127;
        float am = 0.f;
        #pragma unroll
        for (int e = 0; e < K_; e++) am += sA[(p*K_ + e)*STR + c];
        g_aggm[(size_t)(i0+p)*HID_ + c] = am;
    }

    // ---- t = silu(m @ Wx1) -> sB ----
    ZC2();
    gemmT16(g_fWx1[layer], 16, sW, mb0, mb1, ph,
            sA + ra*STR, sA + rb*STR, sA + rc*STR, sA + rd*STR,
            nbase, t, l, tid, cc);
    EPI2_SILU(sB);
    __syncthreads();

    // ---- coef = t @ Wx2 (Nt=2, old tiling; halves duplicate, first writes) ----
    {
        float c2[2][4];
        c2[0][0]=c2[0][1]=c2[0][2]=c2[0][3]=0.f;
        c2[1][0]=c2[1][1]=c2[1][2]=c2[1][3]=0.f;
        gemmT<2>(g_fWx2[layer], 16, sW, mb0, mb1, ph,
                 sB + R0*STR, sB + R1*STR, t, l, tid, c2);
        if (w < 6) {
            #pragma unroll
            for (int n = 0; n < 2; n++) {
                int col = n*8 + 2*t;
                *(float2*)(sCW + R0*16 + col) = make_float2(c2[n][0], c2[n][1]);
                *(float2*)(sCW + R1*16 + col) = make_float2(c2[n][2], c2[n][3]);
            }
        }
    }
    __syncthreads();

    // ---- X update ----
    for (int idx = tid; idx < NPB*XDIM; idx += NT) {
        int p = idx / XDIM, q = idx - p*XDIM, c = q / 3;
        float s = 0.f;
        #pragma unroll
        for (int e = 0; e < K_; e++)
            s += sXD[(p*K_ + e)*XDIM + q] * sCW[(p*K_ + e)*16 + c];
        float cw = g_classcw[S[i0+p]*C_ + c];
        Xout[(size_t)(i0+p)*XDIM + q] =
            Xin[(size_t)(i0+p)*XDIM + q] + s * cw * (1.0f/K_);
    }
}

// ---------------------------------------------------------------------------
// Unified pack kernel (keeps edge_kernel as the 4th launch for ncu)
// ---------------------------------------------------------------------------
__device__ __forceinline__ void pack_frag_one(
    float* dst, const float* __restrict__ W, int f,
    int Ntl, int Kreal, int Ncol, float scale)
{
    int PERQ = Ntl*64;
    int q = f / PERQ, r = f - q*PERQ;
    int n = r >> 6, l2 = r & 63, li = l2 >> 1, b = l2 & 1;
    int t = li & 3, g = li >> 2;
    int k = q*8 + t + b*4, col = n*8 + g;
    float v = (k < Kreal && col < Ncol) ? W[k*Ncol + col] * scale : 0.f;
    dst[f] = __uint_as_float(tf32r(v));
}

__global__ void __launch_bounds__(256) pack_all(
    const float* __restrict__ Wr,  const float* __restrict__ We1,
    const float* __restrict__ We2, const float* __restrict__ Wx1,
    const float* __restrict__ Wx2, const float* __restrict__ Wh1,
    const float* __restrict__ Wh2, const float* __restrict__ Wf1,
    const float* __restrict__ Wf2, const float* __restrict__ be1,
    const float* __restrict__ E_tab, const float* __restrict__ Win,
    const float* __restrict__ Wchan)
{
    int idx = blockIdx.x*256 + threadIdx.x;
    const int S1 = 28*1024, S2 = 48*1024, S3 = 16*1024, S4 = 16*1024, S5 = 16*128;
    const int PL = S1 + S2 + S3 + S4 + S5;
    if (idx < 3*PL) {
        int lyr = idx / PL, f = idx - lyr*PL;
        if (f < S1) { pack_frag_one(g_fWr[lyr],  Wr  + (size_t)lyr*196*128, f, 16, 196, 128, 1.0f/C_); return; }
        f -= S1;
        if (f < S2) { pack_frag_one(g_fWe1[lyr], We1 + (size_t)lyr*384*128, f, 16, 384, 128, 1.f); return; }
        f -= S2;
        if (f < S3) { pack_frag_one(g_fWe2[lyr], We2 + (size_t)lyr*128*128, f, 16, 128, 128, 1.f); return; }
        f -= S3;
        if (f < S4) { pack_frag_one(g_fWx1[lyr], Wx1 + (size_t)lyr*128*128, f, 16, 128, 128, 1.f); return; }
        f -= S4;
        pack_frag_one(g_fWx2[lyr], Wx2 + (size_t)lyr*128*C_, f, 2, 128, C_, 1.f);
        return;
    }
    idx -= 3*PL;
    if (idx < 3*256*128) {
        int lyr = idx / 32768, r = idx & 32767, k = r >> 7, c = r & 127;
        g_Wh1P[lyr][(k>>2)*512 + (c<<2) + (k&3)] = Wh1[idx]; return;
    }
    idx -= 3*256*128;
    if (idx < 3*128*128) {
        int lyr = idx / 16384, r = idx & 16383, k = r >> 7, c = r & 127;
        g_Wh2P[lyr][(k>>2)*512 + (c<<2) + (k&3)] = Wh2[idx]; return;
    }
    idx -= 3*128*128;
    if (idx < 128*128) {
        int k = idx >> 7, c = idx & 127;
        g_Wf1P[(k>>2)*512 + (c<<2) + (k&3)] = Wf1[idx]; return;
    }
    idx -= 128*128;
    if (idx < 128*NCLS_) {
        int k = idx / NCLS_, c = idx - k*NCLS_;
        g_Wf2T[c][k] = Wf2[idx]; return;
    }
    idx -= 128*NCLS_;
    if (idx < 3*HID_) {
        g_be1[idx/HID_][idx%HID_] = be1[idx]; return;
    }
    idx -= 3*HID_;
    if (idx < NCLS_*HID_) {
        int c = idx >> 7, j = idx & 127;
        float acc = 0.f;
        #pragma unroll 4
        for (int k = 0; k < HID_; k++) acc += E_tab[c*HID_ + k] * Win[k*HID_ + j];
        g_classh[c*HID_ + j] = acc;
        return;
    }
    idx -= NCLS_*HID_;
    if (idx < NCLS_) {
        int c = idx;
        float wv[C_]; float mx = -1e30f;
        #pragma unroll
        for (int a = 0; a < C_; a++) { wv[a] = Wchan[c*C_ + a]; mx = fmaxf(mx, wv[a]); }
        float s = 0.f;
        #pragma unroll
        for (int a = 0; a < C_; a++) { wv[a] = expf(wv[a] - mx); s += wv[a]; }
        float inv = 1.0f / s;
        #pragma unroll
        for (int a = 0; a < C_; a++) g_classcw[c*C_ + a] = wv[a] * inv;
    }
}
#define PACK_TOTAL (3*(28*1024+48*1024+16*1024+16*1024+16*128) + 3*256*128 + 3*128*128 + 128*128 + 128*NCLS_ + 3*HID_ + NCLS_*HID_ + NCLS_)

// ---------------------------------------------------------------------------
// kNN on CA coords (channel 1)
// ---------------------------------------------------------------------------
__global__ void __launch_bounds__(256) knn_kernel(const float* __restrict__ X) {
    int b = blockIdx.y;
    int q = blockIdx.x * 256 + threadIdx.x;
    __shared__ float sx[256], sy[256], sz[256];
    float qx = 0.f, qy = 0.f, qz = 0.f;
    if (q < LPC) {
        const float* p = X + ((size_t)(b*LPC + q) * C_ + 1) * 3;
        qx = p[0]; qy = p[1]; qz = p[2];
    }
    float best[K_]; int bidx[K_];
    #pragma unroll
    for (int k = 0; k < K_; k++) { best[k] = 3.0e38f; bidx[k] = 0; }
    for (int base = 0; base < LPC; base += 256) {
        int c = base + threadIdx.x;
        if (c < LPC) {
            const float* p = X + ((size_t)(b*LPC + c) * C_ + 1) * 3;
            sx[threadIdx.x] = p[0]; sy[threadIdx.x] = p[1]; sz[threadIdx.x] = p[2];
        }
        __syncthreads();
        int tl = min(256, LPC - base);
        if (q < LPC) {
            for (int j = 0; j < tl; j++) {
                int cj = base + j;
                if (cj == q) continue;
                float dx = qx - sx[j], dy = qy - sy[j], dz = qz - sz[j];
                float d2 = dx*dx + dy*dy + dz*dz;
                if (d2 < best[K_-1]) {
                    int pos = K_-1;
                    while (pos > 0 && best[pos-1] > d2) {
                        best[pos] = best[pos-1]; bidx[pos] = bidx[pos-1]; pos--;
                    }
                    best[pos] = d2; bidx[pos] = cj;
                }
            }
        }
        __syncthreads();
    }
    if (q < LPC) {
        int n = b*LPC + q;
        #pragma unroll
        for (int k = 0; k < K_; k++) g_dst[n*K_ + k] = b*LPC + bidx[k];
    }
}

__global__ void __launch_bounds__(256) gather_h_kernel(const int* __restrict__ S) {
    int idx = blockIdx.x * 256 + threadIdx.x;
    if (idx < N_ * HID_) {
        int i = idx >> 7, j = idx & 127;
        g_h[idx] = g_classh[S[i]*HID_ + j];
    }
}

// ---------------------------------------------------------------------------
// Node update (f32x2, 16 nodes/block)
// ---------------------------------------------------------------------------
__global__ void __launch_bounds__(128) node_kernel(int layer) {
    const float* W1P = g_Wh1P[layer];
    const float* W2P = g_Wh2P[layer];
    int i0 = blockIdx.x * NNB, tid = threadIdx.x;
    __shared__ __align__(16) float s_h[NNB][HID_];
    __shared__ __align__(16) float s_am[NNB][HID_];
    __shared__ __align__(16) float s_u[NNB][HID_];
    #pragma unroll
    for (int r = 0; r < NNB; r++) {
        s_h[r][tid]  = g_h[(i0+r)*HID_ + tid];
        s_am[r][tid] = g_aggm[(i0+r)*HID_ + tid];
    }
    __syncthreads();
    {
        ull acc[NNB];
        #pragma unroll
        for (int r = 0; r < NNB; r++) acc[r] = 0ULL;
        const float* wp = W1P + (tid << 2);
        #pragma unroll 1
        for (int k4 = 0; k4 < 32; k4++) {
            ulonglong2 wv = ld2u(wp + k4*512);
            #pragma unroll
            for (int r = 0; r < NNB; r++) {
                ulonglong2 a = ld2u(&s_h[r][k4 << 2]);
                fma2(acc[r], a.x, wv.x); fma2(acc[r], a.y, wv.y);
            }
        }
        const float* wp2 = W1P + 32*512 + (tid << 2);
        #pragma unroll 1
        for (int k4 = 0; k4 < 32; k4++) {
            ulonglong2 wv = ld2u(wp2 + k4*512);
            #pragma unroll
            for (int r = 0; r < NNB; r++) {
                ulonglong2 a = ld2u(&s_am[r][k4 << 2]);
                fma2(acc[r], a.x, wv.x); fma2(acc[r], a.y, wv.y);
            }
        }
        #pragma unroll
        for (int r = 0; r < NNB; r++) s_u[r][tid] = silu_f(hadd2(acc[r]));
    }
    __syncthreads();
    {
        ull acc[NNB];
        #pragma unroll
        for (int r = 0; r < NNB; r++) acc[r] = 0ULL;
        const float* wp = W2P + (tid << 2);
        #pragma unroll 1
        for (int k4 = 0; k4 < 32; k4++) {
            ulonglong2 wv = ld2u(wp + k4*512);
            #pragma unroll
            for (int r = 0; r < NNB; r++) {
                ulonglong2 a = ld2u(&s_u[r][k4 << 2]);
                fma2(acc[r], a.x, wv.x); fma2(acc[r], a.y, wv.y);
            }
        }
        #pragma unroll
        for (int r = 0; r < NNB; r++)
            g_h[(i0+r)*HID_ + tid] = s_h[r][tid] + hadd2(acc[r]);
    }
}

__global__ void __launch_bounds__(128) final_kernel(float* __restrict__ out) {
    int i0 = blockIdx.x * NNB, tid = threadIdx.x;
    __shared__ __align__(16) float s1[NNB][HID_];
    __shared__ __align__(16) float s_u[NNB][HID_];
    #pragma unroll
    for (int r = 0; r < NNB; r++)
        s1[r][tid] = silu_f(g_h[(i0+r)*HID_ + tid]);
    __syncthreads();
    {
        ull acc[NNB];
        #pragma unroll
        for (int r = 0; r < NNB; r++) acc[r] = 0ULL;
        const float* wp = g_Wf1P + (tid << 2);
        #pragma unroll 1
        for (int k4 = 0; k4 < 32; k4++) {
            ulonglong2 wv = ld2u(wp + k4*512);
            #pragma unroll
            for (int r = 0; r < NNB; r++) {
                ulonglong2 a = ld2u(&s1[r][k4 << 2]);
                fma2(acc[r], a.x, wv.x); fma2(acc[r], a.y, wv.y);
            }
        }
        #pragma unroll
        for (int r = 0; r < NNB; r++) s_u[r][tid] = silu_f(hadd2(acc[r]));
    }
    __syncthreads();
    for (int q = tid; q < NNB*NCLS_; q += 128) {
        int r = q / NCLS_, c = q - r*NCLS_;
        ull a2 = 0ULL;
        const float* wrow = &g_Wf2T[c][0];
        #pragma unroll 1
        for (int k4 = 0; k4 < 32; k4++) {
            ulonglong2 wv = ld2u(wrow + (k4 << 2));
            ulonglong2 a = ld2u(&s_u[r][k4 << 2]);
            fma2(a2, a.x, wv.x); fma2(a2, a.y, wv.y);
        }
        out[(size_t)(i0+r)*NCLS_ + c] = hadd2(a2);
    }
    const float* Xf = g_X[0];
    for (int idx = tid; idx < NNB*XDIM; idx += 128)
        out[(size_t)N_*NCLS_ + (size_t)i0*XDIM + idx] = Xf[(size_t)i0*XDIM + idx];
}

// ---------------------------------------------------------------------------
#define SMEM_EDGE ((3*M_*STR + 8192 + M_*XDIM + 12*STR + 128 + M_*16)*4 + M_*4 + 16)

extern "C" void kernel_launch(void* const* d_in, const int* in_sizes, int n_in,
                              void* d_out, int out_size)
{
    const float* X     = (const float*)d_in[0];
    const int*   S     = (const int*)  d_in[1];
    const float* E_tab = (const float*)d_in[2];
    const float* Wchan = (const float*)d_in[3];
    const float* Win   = (const float*)d_in[4];
    const float* Wr    = (const float*)d_in[5];
    const float* We1   = (const float*)d_in[6];
    const float* be1   = (const float*)d_in[7];
    const float* We2   = (const float*)d_in[8];
    const float* Wx1   = (const float*)d_in[9];
    const float* Wx2   = (const float*)d_in[10];
    const float* Wh1   = (const float*)d_in[11];
    const float* Wh2   = (const float*)d_in[12];
    const float* Wf1   = (const float*)d_in[13];
    const float* Wf2   = (const float*)d_in[14];
    float* out = (float*)d_out;

    static int smem_set = 0;
    if (!smem_set) {
        cudaFuncSetAttribute(edge_kernel,
            cudaFuncAttributeMaxDynamicSharedMemorySize, SMEM_EDGE);
        smem_set = 1;
    }

    // Launch order: pack_all(1), knn(2), gather(3), edge(4) <- ncu capture slot
    pack_all<<<(PACK_TOTAL + 255)/256, 256>>>(
        Wr, We1, We2, Wx1, Wx2, Wh1, Wh2, Wf1, Wf2, be1, E_tab, Win, Wchan);
    dim3 kg((LPC + 255) / 256, NB);
    knn_kernel<<<kg, 256>>>(X);
    gather_h_kernel<<<(N_*HID_ + 255) / 256, 256>>>(S);

    for (int l = 0; l < 3; l++) {
        edge_kernel<<<N_/NPB, NT, SMEM_EDGE>>>(l, X, S);
        node_kernel<<<N_/NNB, 128>>>(l);
    }
    final_kernel<<<N_/NNB, 128>>>(out);
}